// round 14
// baseline (speedup 1.0000x reference)
#include <cuda_runtime.h>
#include <cstdint>

#define N_V    12288
#define D_F    32
#define N_E    196608
#define THR    128                // threads per block
#define RB     512                // rows per block (4 rows/thread)
#define NBR    (N_V / RB)         // 24
#define SPLIT  12
#define JSEG   (N_V / SPLIT)      // 1024
#define TJ     128                // j-tile
#define SCALE  20.0f
#define INV_S2 (1.0f / (SCALE * SCALE))
#define EPSF   1e-12f
#define BIGI   0x7FFFFFFF
#define BIGF   1e30f

typedef unsigned long long ull;

__device__ uint32_t g_qx[N_V * 8];       // int8-packed quantized rows
__device__ float    g_xf[N_V * D_F];     // float copy of QUANTIZED values (exact)
__device__ int      g_isq[N_V];          // integer squared norms
__device__ float    g_v[N_V];
__device__ int      g_part[N_V * SPLIT * 6];

__device__ __forceinline__ void ffma2(ull &c, ull a, ull b) {
    asm("fma.rn.f32x2 %0, %1, %2, %0;" : "+l"(c) : "l"(a), "l"(b));
}
__device__ __forceinline__ float2 unpack2(ull v) {
    union { ull u; float2 f; } cv; cv.u = v; return cv.f;
}

__device__ __forceinline__ void ins6i(int (&m)[6], int d) {
    int c4 = max(m[4], d);
    int c3 = max(m[3], d);
    int c2 = max(m[2], d);
    int c1 = max(m[1], d);
    int c0 = max(m[0], d);
    m[5] = min(m[5], c4);
    m[4] = min(m[4], c3);
    m[3] = min(m[3], c2);
    m[2] = min(m[2], c1);
    m[0] = min(m[0], d);
    m[1] = min(m[1], c0);
}
__device__ __forceinline__ void ins6f(float (&m)[6], float d) {
    float c4 = fmaxf(m[4], d);
    float c3 = fmaxf(m[3], d);
    float c2 = fmaxf(m[2], d);
    float c1 = fmaxf(m[1], d);
    float c0 = fmaxf(m[0], d);
    m[5] = fminf(m[5], c4);
    m[4] = fminf(m[4], c3);
    m[3] = fminf(m[3], c2);
    m[2] = fminf(m[2], c1);
    m[0] = fminf(m[0], d);
    m[1] = fminf(m[1], c0);
}

// ---------------------------------------------------------------------------
// Kernel 1: quantize x -> int8 (scale 20); also store exact float copy of the
// quantized values (so fp32 FFMA path computes IDENTICAL integers).
// ---------------------------------------------------------------------------
__global__ void conv_kernel(const float* __restrict__ x) {
    int i = blockIdx.x * blockDim.x + threadIdx.x;
    if (i < N_V) {
        const float4* xr = reinterpret_cast<const float4*>(x + (size_t)i * D_F);
        uint32_t pk[8];
        float    xf[32];
        int isq = 0;
        #pragma unroll
        for (int q = 0; q < 8; q++) {
            float4 v = xr[q];
            int q0 = __float2int_rn(fminf(fmaxf(v.x * SCALE, -127.f), 127.f));
            int q1 = __float2int_rn(fminf(fmaxf(v.y * SCALE, -127.f), 127.f));
            int q2 = __float2int_rn(fminf(fmaxf(v.z * SCALE, -127.f), 127.f));
            int q3 = __float2int_rn(fminf(fmaxf(v.w * SCALE, -127.f), 127.f));
            pk[q] = (uint32_t)(q0 & 0xFF) | ((uint32_t)(q1 & 0xFF) << 8) |
                    ((uint32_t)(q2 & 0xFF) << 16) | ((uint32_t)(q3 & 0xFF) << 24);
            isq = __dp4a((int)pk[q], (int)pk[q], isq);
            xf[4 * q]     = (float)q0;
            xf[4 * q + 1] = (float)q1;
            xf[4 * q + 2] = (float)q2;
            xf[4 * q + 3] = (float)q3;
        }
        g_isq[i] = isq;
        uint4* dst = reinterpret_cast<uint4*>(g_qx + (size_t)i * 8);
        dst[0] = make_uint4(pk[0], pk[1], pk[2], pk[3]);
        dst[1] = make_uint4(pk[4], pk[5], pk[6], pk[7]);
        float4* fd = reinterpret_cast<float4*>(g_xf + (size_t)i * D_F);
        #pragma unroll
        for (int q = 0; q < 8; q++)
            fd[q] = make_float4(xf[4 * q], xf[4 * q + 1], xf[4 * q + 2], xf[4 * q + 3]);
    }
}

// ---------------------------------------------------------------------------
// Kernel 2: full-scan knn, DUAL-PIPE: per thread 2 rows via dp4a (int path)
// + 2 rows via packed fp32 FFMA2 (fma pipe). Both paths are exact integer
// arithmetic in quantized space (all magnitudes < 2^21 < 2^24), so results
// are bit-identical; if the int-dot unit and fma pipe are independent, MAC
// throughput doubles vs pure dp4a.
// Grid (24, 12) = 288 CTAs x 128 threads.
// ---------------------------------------------------------------------------
__global__ void __launch_bounds__(THR) knn_kernel() {
    __shared__ uint32_t ti8[TJ * 8];     // int8 j-tile, 4 KB
    __shared__ ull      tf[TJ * 16];     // f32-pair j-tile, 16 KB
    __shared__ int      sqi[TJ];
    __shared__ float    sqf[TJ];

    const int t    = threadIdx.x;
    const int base = blockIdx.x * RB;
    const int jb0  = blockIdx.y * JSEG;

    // rows 0,1: dp4a (packed int8); rows 2,3: FFMA2 (f32 pairs)
    uint32_t rq0[8], rq1[8];
    {
        const uint4* p0 = reinterpret_cast<const uint4*>(g_qx + (size_t)(base + t) * 8);
        const uint4* p1 = reinterpret_cast<const uint4*>(g_qx + (size_t)(base + THR + t) * 8);
        uint4 u = p0[0], v = p0[1];
        rq0[0] = u.x; rq0[1] = u.y; rq0[2] = u.z; rq0[3] = u.w;
        rq0[4] = v.x; rq0[5] = v.y; rq0[6] = v.z; rq0[7] = v.w;
        u = p1[0]; v = p1[1];
        rq1[0] = u.x; rq1[1] = u.y; rq1[2] = u.z; rq1[3] = u.w;
        rq1[4] = v.x; rq1[5] = v.y; rq1[6] = v.z; rq1[7] = v.w;
    }
    ull xf2[16], xf3[16];
    {
        const ull* p2 = reinterpret_cast<const ull*>(g_xf + (size_t)(base + 2 * THR + t) * D_F);
        const ull* p3 = reinterpret_cast<const ull*>(g_xf + (size_t)(base + 3 * THR + t) * D_F);
        #pragma unroll
        for (int k = 0; k < 16; k++) { xf2[k] = p2[k]; xf3[k] = p3[k]; }
    }
    const int   isq0 = g_isq[base + t];
    const int   isq1 = g_isq[base + THR + t];
    const float isqf2 = (float)g_isq[base + 2 * THR + t];
    const float isqf3 = (float)g_isq[base + 3 * THR + t];

    int   m0[6] = {BIGI, BIGI, BIGI, BIGI, BIGI, BIGI};
    int   m1[6] = {BIGI, BIGI, BIGI, BIGI, BIGI, BIGI};
    float m2[6] = {BIGF, BIGF, BIGF, BIGF, BIGF, BIGF};
    float m3[6] = {BIGF, BIGF, BIGF, BIGF, BIGF, BIGF};

    for (int jt = 0; jt < JSEG; jt += TJ) {
        __syncthreads();
        const int jb = jb0 + jt;
        {   // int8 tile: TJ*32B = 4KB, uint4 coalesced
            const uint4* src = reinterpret_cast<const uint4*>(g_qx + (size_t)jb * 8);
            uint4* dst = reinterpret_cast<uint4*>(ti8);
            #pragma unroll
            for (int q = 0; q < 2; q++) dst[t + q * THR] = src[t + q * THR];
        }
        {   // f32 tile: TJ*128B = 16KB, uint4 coalesced
            const uint4* src = reinterpret_cast<const uint4*>(g_xf + (size_t)jb * D_F);
            uint4* dst = reinterpret_cast<uint4*>(tf);
            #pragma unroll
            for (int q = 0; q < 8; q++) dst[t + q * THR] = src[t + q * THR];
        }
        {
            int s = g_isq[jb + t];
            sqi[t] = s;
            sqf[t] = (float)s;
        }
        __syncthreads();

        #pragma unroll 1
        for (int j = 0; j < TJ; j++) {
            const uint4 va = *reinterpret_cast<const uint4*>(&ti8[j * 8]);
            const uint4 vb = *reinterpret_cast<const uint4*>(&ti8[j * 8 + 4]);
            const ulonglong2* jf = reinterpret_cast<const ulonglong2*>(&tf[j * 16]);

            int a0 = __dp4a((int)va.x, (int)rq0[0], 0);
            int a1 = __dp4a((int)va.x, (int)rq1[0], 0);
            a0 = __dp4a((int)va.y, (int)rq0[1], a0);
            a1 = __dp4a((int)va.y, (int)rq1[1], a1);
            a0 = __dp4a((int)va.z, (int)rq0[2], a0);
            a1 = __dp4a((int)va.z, (int)rq1[2], a1);
            a0 = __dp4a((int)va.w, (int)rq0[3], a0);
            a1 = __dp4a((int)va.w, (int)rq1[3], a1);
            a0 = __dp4a((int)vb.x, (int)rq0[4], a0);
            a1 = __dp4a((int)vb.x, (int)rq1[4], a1);
            a0 = __dp4a((int)vb.y, (int)rq0[5], a0);
            a1 = __dp4a((int)vb.y, (int)rq1[5], a1);
            a0 = __dp4a((int)vb.z, (int)rq0[6], a0);
            a1 = __dp4a((int)vb.z, (int)rq1[6], a1);
            a0 = __dp4a((int)vb.w, (int)rq0[7], a0);
            a1 = __dp4a((int)vb.w, (int)rq1[7], a1);

            ull acc2 = 0ull, acc3 = 0ull;   // {0.f, 0.f}
            #pragma unroll
            for (int q = 0; q < 8; q++) {
                ulonglong2 p = jf[q];        // LDS.128 broadcast (4 dims)
                ffma2(acc2, xf2[2 * q],     p.x);
                ffma2(acc3, xf3[2 * q],     p.x);
                ffma2(acc2, xf2[2 * q + 1], p.y);
                ffma2(acc3, xf3[2 * q + 1], p.y);
            }

            const int sj = sqi[j];
            const int d0 = sj + isq0 - a0 - a0;
            const int d1 = sj + isq1 - a1 - a1;
            if (d0 < m0[5]) ins6i(m0, d0);
            if (d1 < m1[5]) ins6i(m1, d1);

            float2 f2 = unpack2(acc2);
            float2 f3 = unpack2(acc3);
            const float sjf = sqf[j];
            float d2 = fmaf(-2.f, f2.x + f2.y, sjf + isqf2);
            float d3 = fmaf(-2.f, f3.x + f3.y, sjf + isqf3);
            if (d2 < m2[5]) ins6f(m2, d2);
            if (d3 < m3[5]) ins6f(m3, d3);
        }
    }

    // write partials (full quantized d^2; float path values are exact ints)
    {
        const int sp6 = SPLIT * 6;
        int* p0 = g_part + (size_t)(base + t)           * sp6 + blockIdx.y * 6;
        int* p1 = g_part + (size_t)(base + THR + t)     * sp6 + blockIdx.y * 6;
        int* p2 = g_part + (size_t)(base + 2 * THR + t) * sp6 + blockIdx.y * 6;
        int* p3 = g_part + (size_t)(base + 3 * THR + t) * sp6 + blockIdx.y * 6;
        #pragma unroll
        for (int q = 0; q < 6; q++) {
            p0[q] = m0[q];
            p1[q] = m1[q];
            p2[q] = (int)m2[q];
            p3[q] = (int)m3[q];
        }
    }
}

// ---------------------------------------------------------------------------
// Kernel 3: merge 12 splits -> vertex filtration value
// v = 1 - sum_{k=1..5} exp(-sqrt(max(d2_k,eps)))/6  (m[0]=0=self dropped)
// ---------------------------------------------------------------------------
__global__ void finalize_vertex_kernel(float* __restrict__ out) {
    int i = blockIdx.x * blockDim.x + threadIdx.x;
    if (i < N_V) {
        const int* src = g_part + (size_t)i * (SPLIT * 6);
        int m[6] = {BIGI, BIGI, BIGI, BIGI, BIGI, BIGI};
        #pragma unroll 4
        for (int k = 0; k < SPLIT * 6; k++) {
            int d = src[k];
            if (d < m[5]) ins6i(m, d);
        }
        float sum = 0.f;
        #pragma unroll
        for (int q = 1; q < 6; q++) {
            float d2 = (float)m[q] * INV_S2;
            sum += expf(-sqrtf(fmaxf(d2, EPSF)));
        }
        float v = 1.f - sum * (1.f / 6.f);
        g_v[i] = v;
        out[2 * i]     = v;
        out[2 * i + 1] = 0.f;
    }
}

// ---------------------------------------------------------------------------
// Kernel 4: edge filtration, 8 edges/warp, 4 independent gathers per lane.
// Reference's per-edge pair sort is a no-op (outputs symmetric in (u,w)).
// ---------------------------------------------------------------------------
__global__ void __launch_bounds__(256) edge_kernel(const float* __restrict__ x,
                                                   const int* __restrict__ ei,
                                                   float* __restrict__ out) {
    const int warp = (blockIdx.x * blockDim.x + threadIdx.x) >> 5;
    const int lane = threadIdx.x & 31;
    const int k    = lane >> 2;          // edge group 0..7
    const int sub  = lane & 3;           // 8-float chunk 0..3
    const int e    = warp * 8 + k;
    if (e < N_E) {
        const int u = ei[e];
        const int w = ei[N_E + e];
        const float4* xu = reinterpret_cast<const float4*>(x + (size_t)u * D_F + sub * 8);
        const float4* xw = reinterpret_cast<const float4*>(x + (size_t)w * D_F + sub * 8);
        float4 a0 = xu[0], a1 = xu[1];
        float4 b0 = xw[0], b1 = xw[1];
        float dx = a0.x - b0.x, dy = a0.y - b0.y;
        float dz = a0.z - b0.z, dw = a0.w - b0.w;
        float s = dx * dx + dy * dy + dz * dz + dw * dw;
        dx = a1.x - b1.x; dy = a1.y - b1.y;
        dz = a1.z - b1.z; dw = a1.w - b1.w;
        s += dx * dx + dy * dy + dz * dz + dw * dw;
        s += __shfl_xor_sync(0xFFFFFFFFu, s, 1);
        s += __shfl_xor_sync(0xFFFFFFFFu, s, 2);
        if (sub == 0) {
            float n  = sqrtf(fmaxf(s, EPSF));
            float ev = fmaxf(g_v[u], g_v[w]);
            *reinterpret_cast<float2*>(out + 2 * (N_V + e)) =
                make_float2(ev, 1.f - expf(-n));
        }
    }
}

// ---------------------------------------------------------------------------
extern "C" void kernel_launch(void* const* d_in, const int* in_sizes, int n_in,
                              void* d_out, int out_size) {
    (void)in_sizes; (void)n_in; (void)out_size;
    const float* x   = (const float*)d_in[0];
    const int*   ei  = (const int*)d_in[1];
    float*       out = (float*)d_out;

    conv_kernel<<<(N_V + 255) / 256, 256>>>(x);

    dim3 grid(NBR, SPLIT);
    knn_kernel<<<grid, THR>>>();

    finalize_vertex_kernel<<<(N_V + 255) / 256, 256>>>(out);
    edge_kernel<<<(N_E / 8 + 7) / 8, 256>>>(x, ei, out);
}